// round 4
// baseline (speedup 1.0000x reference)
#include <cuda_runtime.h>
#include <cuda_bf16.h>
#include <cuda_fp16.h>
#include <cstdint>

// ---------------- problem dims ----------------
#define MM 16384
#define DD 512
#define UU 512
#define KK 1024
#define NN 2048

// ---------------- GEMM tiling ----------------
#define BM 128
#define BN 128
#define BK 32
#define NKT (KK / BK)          // 32
#define LDT 40                 // padded leading dim (halfwords)
#define TILE_ELEMS (BM * LDT)  // 5120

// ---------------- device scratch ----------------
__device__ __align__(16) __half         g_Ahi[(size_t)MM * KK];  // fp16(a)
__device__ __align__(16) __nv_bfloat16  g_Abf[(size_t)MM * KK];  // bf16(a)
__device__ __align__(16) __half         g_Bhi[(size_t)NN * KK];  // fp16(b), permuted rows
__device__ __align__(16) __nv_bfloat16  g_Blo[(size_t)NN * KK];  // bf16(b - fp16(b)), permuted

// ---------------- prep A ----------------
__global__ void __launch_bounds__(256) prep_A_kernel(const float* __restrict__ x,
                                                     const float* __restrict__ h) {
    int gi = blockIdx.x * 256 + threadIdx.x;
    int b = gi >> 7;
    int k0 = (gi & 127) * 8;
    const float* src = (k0 < DD) ? (x + (size_t)b * DD + k0)
                                 : (h + (size_t)b * UU + (k0 - DD));
    float4 v0 = *reinterpret_cast<const float4*>(src);
    float4 v1 = *reinterpret_cast<const float4*>(src + 4);
    float v[8] = {v0.x, v0.y, v0.z, v0.w, v1.x, v1.y, v1.z, v1.w};
    __half hh[8];
    __nv_bfloat16 bb[8];
#pragma unroll
    for (int j = 0; j < 8; j++) {
        hh[j] = __float2half_rn(v[j]);
        bb[j] = __float2bfloat16_rn(v[j]);
    }
    size_t off = (size_t)b * KK + k0;
    *reinterpret_cast<uint4*>(&g_Ahi[off]) = *reinterpret_cast<uint4*>(hh);
    *reinterpret_cast<uint4*>(&g_Abf[off]) = *reinterpret_cast<uint4*>(bb);
}

// ---------------- prep B: transpose + permute (p = u*4 + gate) ----------------
__global__ void prep_B_kernel(const float* __restrict__ Wk, const float* __restrict__ Wr) {
    __shared__ float t[32][33];
    int n0 = blockIdx.x * 32, k0 = blockIdx.y * 32;
    int tn = threadIdx.x, tk = threadIdx.y;  // block (32, 8)
#pragma unroll
    for (int j = 0; j < 32; j += 8) {
        int k = k0 + tk + j;
        float v = (k < DD) ? Wk[(size_t)k * NN + n0 + tn]
                           : Wr[(size_t)(k - DD) * NN + n0 + tn];
        t[tk + j][tn] = v;
    }
    __syncthreads();
#pragma unroll
    for (int j = 0; j < 32; j += 8) {
        int n = n0 + tk + j;
        int k = k0 + tn;
        int p = ((n & 511) << 2) + (n >> 9);  // unit*4 + gate
        float v = t[tn][tk + j];
        __half hv = __float2half_rn(v);
        g_Bhi[(size_t)p * KK + k] = hv;
        g_Blo[(size_t)p * KK + k] = __float2bfloat16_rn(v - __half2float(hv));
    }
}

// ---------------- fused GEMM (2-pass mma.sync, ldmatrix) + gates ----------------
struct Stage {
    __half        Ahi[TILE_ELEMS];
    __nv_bfloat16 Abf[TILE_ELEMS];
    __half        Bhi[TILE_ELEMS];
    __nv_bfloat16 Blo[TILE_ELEMS];
};  // 40960 bytes

__device__ __forceinline__ void cp_async16(void* dst, const void* src) {
    unsigned d = (unsigned)__cvta_generic_to_shared(dst);
    asm volatile("cp.async.cg.shared.global [%0], [%1], 16;" :: "r"(d), "l"(src) : "memory");
}

__device__ __forceinline__ void ldsm_x4(unsigned r[4], uint32_t addr) {
    asm volatile("ldmatrix.sync.aligned.m8n8.x4.shared.b16 {%0,%1,%2,%3}, [%4];"
                 : "=r"(r[0]), "=r"(r[1]), "=r"(r[2]), "=r"(r[3]) : "r"(addr));
}

__device__ __forceinline__ void mma_f16(float c[4], const unsigned a[4],
                                        unsigned b0, unsigned b1) {
    asm volatile(
        "mma.sync.aligned.m16n8k16.row.col.f32.f16.f16.f32 "
        "{%0,%1,%2,%3}, {%4,%5,%6,%7}, {%8,%9}, {%0,%1,%2,%3};"
        : "+f"(c[0]), "+f"(c[1]), "+f"(c[2]), "+f"(c[3])
        : "r"(a[0]), "r"(a[1]), "r"(a[2]), "r"(a[3]), "r"(b0), "r"(b1));
}

__device__ __forceinline__ void mma_bf16(float c[4], const unsigned a[4],
                                         unsigned b0, unsigned b1) {
    asm volatile(
        "mma.sync.aligned.m16n8k16.row.col.f32.bf16.bf16.f32 "
        "{%0,%1,%2,%3}, {%4,%5,%6,%7}, {%8,%9}, {%0,%1,%2,%3};"
        : "+f"(c[0]), "+f"(c[1]), "+f"(c[2]), "+f"(c[3])
        : "r"(a[0]), "r"(a[1]), "r"(a[2]), "r"(a[3]), "r"(b0), "r"(b1));
}

__device__ __forceinline__ float sigf(float x) { return 1.0f / (1.0f + __expf(-x)); }

#define LDZ 132  // padded z stride in floats

__global__ void __launch_bounds__(256)
lstm_gemm_kernel(const float* __restrict__ c_tm1,
                 const float* __restrict__ pw,
                 const float* __restrict__ bias,
                 float* __restrict__ out) {
    extern __shared__ __align__(16) unsigned char smem_raw[];
    Stage* stages = reinterpret_cast<Stage*>(smem_raw);

    const int tid = threadIdx.x;
    const int lane = tid & 31;
    const int wid = tid >> 5;
    const int mw = (wid >> 1) * 32;  // 4 warps in M
    const int nw = (wid & 1) * 64;   // 2 warps in N
    const int m0 = blockIdx.y * BM;
    const int n0 = blockIdx.x * BN;
    const int r = lane >> 2, q = lane & 3;

    // ldmatrix per-lane row/offset: rows (lane&7) + 8*((lane>>3)&1), k-half (lane>>4)
    const int lrow = (lane & 7) + ((lane >> 3) & 1) * 8;
    const int lkof = (lane >> 4) * 16;  // bytes (8 halfwords)

    auto load_stage = [&](int s, int kt) {
        Stage* st = &stages[s];
        int k0 = kt * BK;
        for (int c = tid; c < 512; c += 256) {
            int row = c >> 2, seg = c & 3;
            int soff = row * LDT + seg * 8;
            size_t aoff = (size_t)(m0 + row) * KK + k0 + seg * 8;
            size_t boff = (size_t)(n0 + row) * KK + k0 + seg * 8;
            cp_async16(&st->Ahi[soff], &g_Ahi[aoff]);
            cp_async16(&st->Abf[soff], &g_Abf[aoff]);
            cp_async16(&st->Bhi[soff], &g_Bhi[boff]);
            cp_async16(&st->Blo[soff], &g_Blo[boff]);
        }
        asm volatile("cp.async.commit_group;" ::: "memory");
    };

    float acc[2][8][4];
#pragma unroll
    for (int a = 0; a < 2; a++)
#pragma unroll
        for (int b = 0; b < 8; b++)
#pragma unroll
            for (int c = 0; c < 4; c++) acc[a][b][c] = 0.0f;

    load_stage(0, 0);
    load_stage(1, 1);

    for (int kt = 0; kt < NKT; kt++) {
        asm volatile("cp.async.wait_group 1;" ::: "memory");
        __syncthreads();
        if (kt + 2 < NKT) load_stage((kt + 2) % 3, kt + 2);
        else asm volatile("cp.async.commit_group;" ::: "memory");

        const Stage* st = &stages[kt % 3];
#pragma unroll
        for (int kk = 0; kk < BK; kk += 16) {
            // ---- fragment loads via ldmatrix.x4 ----
            unsigned ah[2][4], ab[2][4];
#pragma unroll
            for (int ms = 0; ms < 2; ms++) {
                uint32_t boff = (uint32_t)(((mw + ms * 16 + lrow) * LDT + kk) * 2 + lkof);
                ldsm_x4(ah[ms], (unsigned)__cvta_generic_to_shared(
                                    (const char*)st->Ahi + boff));
                ldsm_x4(ab[ms], (unsigned)__cvta_generic_to_shared(
                                    (const char*)st->Abf + boff));
            }
            unsigned bh[4][4], bl[4][4];  // [npair][{b0(ns even),b0(odd),b1(even),b1(odd)}]
#pragma unroll
            for (int p = 0; p < 4; p++) {
                uint32_t boff = (uint32_t)(((nw + p * 16 + lrow) * LDT + kk) * 2 + lkof);
                ldsm_x4(bh[p], (unsigned)__cvta_generic_to_shared(
                                   (const char*)st->Bhi + boff));
                ldsm_x4(bl[p], (unsigned)__cvta_generic_to_shared(
                                   (const char*)st->Blo + boff));
            }
            // ---- all f16 MMAs (main product) ----
#pragma unroll
            for (int p = 0; p < 4; p++)
#pragma unroll
                for (int e = 0; e < 2; e++)
#pragma unroll
                    for (int ms = 0; ms < 2; ms++)
                        mma_f16(acc[ms][p * 2 + e], ah[ms], bh[p][e], bh[p][e + 2]);
            // ---- all bf16 MMAs (correction) ----
#pragma unroll
            for (int p = 0; p < 4; p++)
#pragma unroll
                for (int e = 0; e < 2; e++)
#pragma unroll
                    for (int ms = 0; ms < 2; ms++)
                        mma_bf16(acc[ms][p * 2 + e], ab[ms], bl[p][e], bl[p][e + 2]);
        }
    }

    // ---------------- fused gate epilogue ----------------
    __syncthreads();
    float* zsm = reinterpret_cast<float*>(smem_raw);  // [128][LDZ]

#pragma unroll
    for (int ms = 0; ms < 2; ms++)
#pragma unroll
        for (int ns = 0; ns < 8; ns++) {
            int row = mw + ms * 16 + r;
            int col = nw + ns * 8 + 2 * q;
            *(float2*)&zsm[row * LDZ + col] = make_float2(acc[ms][ns][0], acc[ms][ns][1]);
            *(float2*)&zsm[(row + 8) * LDZ + col] = make_float2(acc[ms][ns][2], acc[ms][ns][3]);
        }
    __syncthreads();

    {
        const int ul = tid & 31;
        const int u = blockIdx.x * 32 + ul;
        const float bi = bias[u];
        const float bf = bias[512 + u];
        const float bg = bias[1024 + u];
        const float bo = bias[1536 + u];
        const float pwi = pw[u * 3 + 0];
        const float pwf = pw[u * 3 + 1];
        const float pwo = pw[u * 3 + 2];
#pragma unroll
        for (int it = 0; it < 16; it++) {
            int row = (tid >> 5) * 16 + it;
            int m = m0 + row;
            float4 zz = *reinterpret_cast<const float4*>(&zsm[row * LDZ + ul * 4]);
            float cprev = c_tm1[(size_t)m * UU + u];
            float iv = sigf(zz.x + bi + cprev * pwi);
            float fv = sigf(zz.y + bf + cprev * pwf);
            float gv = tanhf(zz.z + bg);
            float cc = fv * cprev + iv * gv;
            float ov = sigf(zz.w + bo + cc * pwo);
            out[(size_t)m * UU + u] = ov * tanhf(cc);
            out[(size_t)MM * UU + (size_t)m * UU + u] = cc;
        }
    }
}

// ---------------- launch ----------------
extern "C" void kernel_launch(void* const* d_in, const int* in_sizes, int n_in,
                              void* d_out, int out_size) {
    const float* x    = (const float*)d_in[0];
    const float* h    = (const float*)d_in[1];
    const float* c    = (const float*)d_in[2];
    const float* Wk   = (const float*)d_in[3];
    const float* Wr   = (const float*)d_in[4];
    const float* pw   = (const float*)d_in[5];
    const float* bias = (const float*)d_in[6];
    float* out = (float*)d_out;

    cudaFuncSetAttribute(lstm_gemm_kernel, cudaFuncAttributeMaxDynamicSharedMemorySize,
                         (int)(3 * sizeof(Stage)));

    prep_A_kernel<<<(MM * KK / 8) / 256, 256>>>(x, h);
    prep_B_kernel<<<dim3(NN / 32, KK / 32), dim3(32, 8)>>>(Wk, Wr);
    lstm_gemm_kernel<<<dim3(NN / BN, MM / BM), 256, 3 * sizeof(Stage)>>>(c, pw, bias, out);
}

// round 5
// speedup vs baseline: 1.0672x; 1.0672x over previous
#include <cuda_runtime.h>
#include <cuda_bf16.h>
#include <cuda_fp16.h>
#include <cstdint>

// ---------------- problem dims ----------------
#define MM 16384
#define DD 512
#define UU 512
#define KK 1024
#define NN 2048

// ---------------- GEMM tiling ----------------
#define BM 128
#define BN 128
#define BK 32
#define NKT (KK / BK)          // 32
#define NSTAGES 6
#define LDT 40                 // padded leading dim (halfwords)
#define TILE_ELEMS (BM * LDT)  // 5120

// ---------------- device scratch ----------------
__device__ __align__(16) __half g_A[(size_t)MM * KK];    // fp16(a)
__device__ __align__(16) __half g_Bhi[(size_t)NN * KK];  // fp16(b), permuted rows
__device__ __align__(16) __half g_Blo[(size_t)NN * KK];  // fp16(b - fp16(b)), permuted

// ---------------- prep A ----------------
__global__ void __launch_bounds__(256) prep_A_kernel(const float* __restrict__ x,
                                                     const float* __restrict__ h) {
    int gi = blockIdx.x * 256 + threadIdx.x;
    int b = gi >> 7;
    int k0 = (gi & 127) * 8;
    const float* src = (k0 < DD) ? (x + (size_t)b * DD + k0)
                                 : (h + (size_t)b * UU + (k0 - DD));
    float4 v0 = *reinterpret_cast<const float4*>(src);
    float4 v1 = *reinterpret_cast<const float4*>(src + 4);
    float v[8] = {v0.x, v0.y, v0.z, v0.w, v1.x, v1.y, v1.z, v1.w};
    __half hh[8];
#pragma unroll
    for (int j = 0; j < 8; j++) hh[j] = __float2half_rn(v[j]);
    *reinterpret_cast<uint4*>(&g_A[(size_t)b * KK + k0]) = *reinterpret_cast<uint4*>(hh);
}

// ---------------- prep B: transpose + permute (p = u*4 + gate), fp16 hi/lo ----------------
__global__ void prep_B_kernel(const float* __restrict__ Wk, const float* __restrict__ Wr) {
    __shared__ float t[32][33];
    int n0 = blockIdx.x * 32, k0 = blockIdx.y * 32;
    int tn = threadIdx.x, tk = threadIdx.y;  // block (32, 8)
#pragma unroll
    for (int j = 0; j < 32; j += 8) {
        int k = k0 + tk + j;
        float v = (k < DD) ? Wk[(size_t)k * NN + n0 + tn]
                           : Wr[(size_t)(k - DD) * NN + n0 + tn];
        t[tk + j][tn] = v;
    }
    __syncthreads();
#pragma unroll
    for (int j = 0; j < 32; j += 8) {
        int n = n0 + tk + j;
        int k = k0 + tn;
        int p = ((n & 511) << 2) + (n >> 9);  // unit*4 + gate
        float v = t[tn][tk + j];
        __half hv = __float2half_rn(v);
        g_Bhi[(size_t)p * KK + k] = hv;
        g_Blo[(size_t)p * KK + k] = __float2half_rn(v - __half2float(hv));
    }
}

// ---------------- fused GEMM (2-pass all-f16 mma.sync) + gates ----------------
struct Stage {
    __half A[TILE_ELEMS];
    __half Bhi[TILE_ELEMS];
    __half Blo[TILE_ELEMS];
};  // 30720 bytes

__device__ __forceinline__ void cp_async16(void* dst, const void* src) {
    unsigned d = (unsigned)__cvta_generic_to_shared(dst);
    asm volatile("cp.async.cg.shared.global [%0], [%1], 16;" :: "r"(d), "l"(src) : "memory");
}

__device__ __forceinline__ void ldsm_x4(unsigned r[4], uint32_t addr) {
    asm volatile("ldmatrix.sync.aligned.m8n8.x4.shared.b16 {%0,%1,%2,%3}, [%4];"
                 : "=r"(r[0]), "=r"(r[1]), "=r"(r[2]), "=r"(r[3]) : "r"(addr));
}

__device__ __forceinline__ void mma_f16(float c[4], const unsigned a[4],
                                        unsigned b0, unsigned b1) {
    asm volatile(
        "mma.sync.aligned.m16n8k16.row.col.f32.f16.f16.f32 "
        "{%0,%1,%2,%3}, {%4,%5,%6,%7}, {%8,%9}, {%0,%1,%2,%3};"
        : "+f"(c[0]), "+f"(c[1]), "+f"(c[2]), "+f"(c[3])
        : "r"(a[0]), "r"(a[1]), "r"(a[2]), "r"(a[3]), "r"(b0), "r"(b1));
}

__device__ __forceinline__ float sigf(float x) { return 1.0f / (1.0f + __expf(-x)); }

#define LDZ 132  // padded z stride in floats

__global__ void __launch_bounds__(256)
lstm_gemm_kernel(const float* __restrict__ c_tm1,
                 const float* __restrict__ pw,
                 const float* __restrict__ bias,
                 float* __restrict__ out) {
    extern __shared__ __align__(16) unsigned char smem_raw[];
    Stage* stages = reinterpret_cast<Stage*>(smem_raw);

    const int tid = threadIdx.x;
    const int lane = tid & 31;
    const int wid = tid >> 5;
    const int mw = (wid >> 1) * 32;  // 4 warps in M
    const int nw = (wid & 1) * 64;   // 2 warps in N
    const int m0 = blockIdx.y * BM;
    const int n0 = blockIdx.x * BN;
    const int r = lane >> 2, q = lane & 3;

    const int lrow = (lane & 7) + ((lane >> 3) & 1) * 8;
    const int lkof = (lane >> 4) * 16;  // bytes

    auto load_stage = [&](int s, int kt) {
        Stage* st = &stages[s];
        int k0 = kt * BK;
        for (int c = tid; c < 512; c += 256) {
            int row = c >> 2, seg = c & 3;
            int soff = row * LDT + seg * 8;
            size_t aoff = (size_t)(m0 + row) * KK + k0 + seg * 8;
            size_t boff = (size_t)(n0 + row) * KK + k0 + seg * 8;
            cp_async16(&st->A[soff], &g_A[aoff]);
            cp_async16(&st->Bhi[soff], &g_Bhi[boff]);
            cp_async16(&st->Blo[soff], &g_Blo[boff]);
        }
        asm volatile("cp.async.commit_group;" ::: "memory");
    };

    float acc[2][8][4];
#pragma unroll
    for (int a = 0; a < 2; a++)
#pragma unroll
        for (int b = 0; b < 8; b++)
#pragma unroll
            for (int c = 0; c < 4; c++) acc[a][b][c] = 0.0f;

#pragma unroll
    for (int s = 0; s < NSTAGES - 1; s++) load_stage(s, s);

    for (int kt = 0; kt < NKT; kt++) {
        asm volatile("cp.async.wait_group %0;" :: "n"(NSTAGES - 2) : "memory");
        __syncthreads();
        if (kt + NSTAGES - 1 < NKT)
            load_stage((kt + NSTAGES - 1) % NSTAGES, kt + NSTAGES - 1);
        else
            asm volatile("cp.async.commit_group;" ::: "memory");

        const Stage* st = &stages[kt % NSTAGES];
#pragma unroll
        for (int kk = 0; kk < BK; kk += 16) {
            unsigned ah[2][4];
#pragma unroll
            for (int ms = 0; ms < 2; ms++) {
                uint32_t boff = (uint32_t)(((mw + ms * 16 + lrow) * LDT + kk) * 2 + lkof);
                ldsm_x4(ah[ms], (unsigned)__cvta_generic_to_shared(
                                    (const char*)st->A + boff));
            }
            unsigned bh[4][4], bl[4][4];
#pragma unroll
            for (int p = 0; p < 4; p++) {
                uint32_t boff = (uint32_t)(((nw + p * 16 + lrow) * LDT + kk) * 2 + lkof);
                ldsm_x4(bh[p], (unsigned)__cvta_generic_to_shared(
                                   (const char*)st->Bhi + boff));
                ldsm_x4(bl[p], (unsigned)__cvta_generic_to_shared(
                                   (const char*)st->Blo + boff));
            }
            // main product
#pragma unroll
            for (int p = 0; p < 4; p++)
#pragma unroll
                for (int e = 0; e < 2; e++)
#pragma unroll
                    for (int ms = 0; ms < 2; ms++)
                        mma_f16(acc[ms][p * 2 + e], ah[ms], bh[p][e], bh[p][e + 2]);
            // correction (b_lo in fp16 subnormal range; same A fragments)
#pragma unroll
            for (int p = 0; p < 4; p++)
#pragma unroll
                for (int e = 0; e < 2; e++)
#pragma unroll
                    for (int ms = 0; ms < 2; ms++)
                        mma_f16(acc[ms][p * 2 + e], ah[ms], bl[p][e], bl[p][e + 2]);
        }
    }

    // ---------------- fused gate epilogue ----------------
    __syncthreads();
    float* zsm = reinterpret_cast<float*>(smem_raw);  // [128][LDZ]

#pragma unroll
    for (int ms = 0; ms < 2; ms++)
#pragma unroll
        for (int ns = 0; ns < 8; ns++) {
            int row = mw + ms * 16 + r;
            int col = nw + ns * 8 + 2 * q;
            *(float2*)&zsm[row * LDZ + col] = make_float2(acc[ms][ns][0], acc[ms][ns][1]);
            *(float2*)&zsm[(row + 8) * LDZ + col] = make_float2(acc[ms][ns][2], acc[ms][ns][3]);
        }
    __syncthreads();

    {
        const int ul = tid & 31;
        const int u = blockIdx.x * 32 + ul;
        const float bi = bias[u];
        const float bf = bias[512 + u];
        const float bg = bias[1024 + u];
        const float bo = bias[1536 + u];
        const float pwi = pw[u * 3 + 0];
        const float pwf = pw[u * 3 + 1];
        const float pwo = pw[u * 3 + 2];
#pragma unroll
        for (int it = 0; it < 16; it++) {
            int row = (tid >> 5) * 16 + it;
            int m = m0 + row;
            float4 zz = *reinterpret_cast<const float4*>(&zsm[row * LDZ + ul * 4]);
            float cprev = c_tm1[(size_t)m * UU + u];
            float iv = sigf(zz.x + bi + cprev * pwi);
            float fv = sigf(zz.y + bf + cprev * pwf);
            float gv = tanhf(zz.z + bg);
            float cc = fv * cprev + iv * gv;
            float ov = sigf(zz.w + bo + cc * pwo);
            out[(size_t)m * UU + u] = ov * tanhf(cc);
            out[(size_t)MM * UU + (size_t)m * UU + u] = cc;
        }
    }
}

// ---------------- launch ----------------
extern "C" void kernel_launch(void* const* d_in, const int* in_sizes, int n_in,
                              void* d_out, int out_size) {
    const float* x    = (const float*)d_in[0];
    const float* h    = (const float*)d_in[1];
    const float* c    = (const float*)d_in[2];
    const float* Wk   = (const float*)d_in[3];
    const float* Wr   = (const float*)d_in[4];
    const float* pw   = (const float*)d_in[5];
    const float* bias = (const float*)d_in[6];
    float* out = (float*)d_out;

    cudaFuncSetAttribute(lstm_gemm_kernel, cudaFuncAttributeMaxDynamicSharedMemorySize,
                         (int)(NSTAGES * sizeof(Stage)));

    prep_A_kernel<<<(MM * KK / 8) / 256, 256>>>(x, h);
    prep_B_kernel<<<dim3(NN / 32, KK / 32), dim3(32, 8)>>>(Wk, Wr);
    lstm_gemm_kernel<<<dim3(NN / BN, MM / BM), 256, NSTAGES * sizeof(Stage)>>>(c, pw, bias, out);
}

// round 6
// speedup vs baseline: 1.3580x; 1.2725x over previous
#include <cuda_runtime.h>
#include <cuda_bf16.h>
#include <cuda_fp16.h>
#include <cstdint>

// ---------------- problem dims ----------------
#define MM 16384
#define DD 512
#define UU 512
#define KK 1024
#define NN 2048

// ---------------- GEMM tiling ----------------
#define BM 128
#define BN 256
#define BK 32
#define NKT (KK / BK)            // 32
#define NSTAGES 4
#define LDT 40                   // padded leading dim (halfwords)
#define A_ELEMS (BM * LDT)       // 5120
#define B_ELEMS (BN * LDT)       // 10240

// ---------------- device scratch ----------------
__device__ __align__(16) __half g_A[(size_t)MM * KK];    // fp16(a)
__device__ __align__(16) __half g_Bhi[(size_t)NN * KK];  // fp16(b), permuted rows
__device__ __align__(16) __half g_Blo[(size_t)NN * KK];  // fp16(b - fp16(b)), permuted

// ---------------- prep A ----------------
__global__ void __launch_bounds__(256) prep_A_kernel(const float* __restrict__ x,
                                                     const float* __restrict__ h) {
    int gi = blockIdx.x * 256 + threadIdx.x;
    int b = gi >> 7;
    int k0 = (gi & 127) * 8;
    const float* src = (k0 < DD) ? (x + (size_t)b * DD + k0)
                                 : (h + (size_t)b * UU + (k0 - DD));
    float4 v0 = *reinterpret_cast<const float4*>(src);
    float4 v1 = *reinterpret_cast<const float4*>(src + 4);
    float v[8] = {v0.x, v0.y, v0.z, v0.w, v1.x, v1.y, v1.z, v1.w};
    __half hh[8];
#pragma unroll
    for (int j = 0; j < 8; j++) hh[j] = __float2half_rn(v[j]);
    *reinterpret_cast<uint4*>(&g_A[(size_t)b * KK + k0]) = *reinterpret_cast<uint4*>(hh);
}

// ---------------- prep B: transpose + permute (p = u*4 + gate), fp16 hi/lo ----------------
__global__ void prep_B_kernel(const float* __restrict__ Wk, const float* __restrict__ Wr) {
    __shared__ float t[32][33];
    int n0 = blockIdx.x * 32, k0 = blockIdx.y * 32;
    int tn = threadIdx.x, tk = threadIdx.y;  // block (32, 8)
#pragma unroll
    for (int j = 0; j < 32; j += 8) {
        int k = k0 + tk + j;
        float v = (k < DD) ? Wk[(size_t)k * NN + n0 + tn]
                           : Wr[(size_t)(k - DD) * NN + n0 + tn];
        t[tk + j][tn] = v;
    }
    __syncthreads();
#pragma unroll
    for (int j = 0; j < 32; j += 8) {
        int n = n0 + tk + j;
        int k = k0 + tn;
        int p = ((n & 511) << 2) + (n >> 9);  // unit*4 + gate
        float v = t[tn][tk + j];
        __half hv = __float2half_rn(v);
        g_Bhi[(size_t)p * KK + k] = hv;
        g_Blo[(size_t)p * KK + k] = __float2half_rn(v - __half2float(hv));
    }
}

// ---------------- fused GEMM (2-pass all-f16 mma.sync, 512 thr) + gates ----------------
struct Stage {
    __half A[A_ELEMS];
    __half Bhi[B_ELEMS];
    __half Blo[B_ELEMS];
};  // 51200 bytes

__device__ __forceinline__ void cp_async16(void* dst, const void* src) {
    unsigned d = (unsigned)__cvta_generic_to_shared(dst);
    asm volatile("cp.async.cg.shared.global [%0], [%1], 16;" :: "r"(d), "l"(src) : "memory");
}

__device__ __forceinline__ void ldsm_x4(unsigned r[4], uint32_t addr) {
    asm volatile("ldmatrix.sync.aligned.m8n8.x4.shared.b16 {%0,%1,%2,%3}, [%4];"
                 : "=r"(r[0]), "=r"(r[1]), "=r"(r[2]), "=r"(r[3]) : "r"(addr));
}

__device__ __forceinline__ void mma_f16(float c[4], const unsigned a[4],
                                        unsigned b0, unsigned b1) {
    asm volatile(
        "mma.sync.aligned.m16n8k16.row.col.f32.f16.f16.f32 "
        "{%0,%1,%2,%3}, {%4,%5,%6,%7}, {%8,%9}, {%0,%1,%2,%3};"
        : "+f"(c[0]), "+f"(c[1]), "+f"(c[2]), "+f"(c[3])
        : "r"(a[0]), "r"(a[1]), "r"(a[2]), "r"(a[3]), "r"(b0), "r"(b1));
}

__device__ __forceinline__ float sigf(float x) { return 1.0f / (1.0f + __expf(-x)); }

#define LDZ 260  // padded z stride in floats

__global__ void __launch_bounds__(512)
lstm_gemm_kernel(const float* __restrict__ c_tm1,
                 const float* __restrict__ pw,
                 const float* __restrict__ bias,
                 float* __restrict__ out) {
    extern __shared__ __align__(16) unsigned char smem_raw[];
    Stage* stages = reinterpret_cast<Stage*>(smem_raw);

    const int tid = threadIdx.x;
    const int lane = tid & 31;
    const int wid = tid >> 5;        // 0..15
    const int mw = (wid >> 2) * 32;  // 4 warps in M
    const int nw = (wid & 3) * 64;   // 4 warps in N
    const int m0 = blockIdx.y * BM;
    const int n0 = blockIdx.x * BN;
    const int r = lane >> 2, q = lane & 3;

    const int lrow = (lane & 7) + ((lane >> 3) & 1) * 8;
    const int lkof = (lane >> 4) * 16;  // bytes

    auto load_stage = [&](int s, int kt) {
        Stage* st = &stages[s];
        int k0 = kt * BK;
        {   // A: 512 16B-chunks, 1 per thread
            int row = tid >> 2, seg = tid & 3;
            cp_async16(&st->A[row * LDT + seg * 8],
                       &g_A[(size_t)(m0 + row) * KK + k0 + seg * 8]);
        }
#pragma unroll
        for (int i = 0; i < 2; i++) {  // B: 1024 chunks each, 2 per thread
            int c = tid + i * 512;
            int row = c >> 2, seg = c & 3;
            int soff = row * LDT + seg * 8;
            size_t boff = (size_t)(n0 + row) * KK + k0 + seg * 8;
            cp_async16(&st->Bhi[soff], &g_Bhi[boff]);
            cp_async16(&st->Blo[soff], &g_Blo[boff]);
        }
        asm volatile("cp.async.commit_group;" ::: "memory");
    };

    float acc[2][8][4];
#pragma unroll
    for (int a = 0; a < 2; a++)
#pragma unroll
        for (int b = 0; b < 8; b++)
#pragma unroll
            for (int c = 0; c < 4; c++) acc[a][b][c] = 0.0f;

#pragma unroll
    for (int s = 0; s < NSTAGES - 1; s++) load_stage(s, s);

    for (int kt = 0; kt < NKT; kt++) {
        asm volatile("cp.async.wait_group %0;" :: "n"(NSTAGES - 2) : "memory");
        __syncthreads();
        if (kt + NSTAGES - 1 < NKT)
            load_stage((kt + NSTAGES - 1) % NSTAGES, kt + NSTAGES - 1);
        else
            asm volatile("cp.async.commit_group;" ::: "memory");

        const Stage* st = &stages[kt % NSTAGES];
#pragma unroll
        for (int kk = 0; kk < BK; kk += 16) {
            unsigned ah[2][4];
#pragma unroll
            for (int ms = 0; ms < 2; ms++) {
                uint32_t boff = (uint32_t)(((mw + ms * 16 + lrow) * LDT + kk) * 2 + lkof);
                ldsm_x4(ah[ms], (unsigned)__cvta_generic_to_shared(
                                    (const char*)st->A + boff));
            }
            // per N-pair: load bh/bl, fire main + correction (short reg lifetimes)
#pragma unroll
            for (int p = 0; p < 4; p++) {
                uint32_t boff = (uint32_t)(((nw + p * 16 + lrow) * LDT + kk) * 2 + lkof);
                unsigned bh[4], bl[4];
                ldsm_x4(bh, (unsigned)__cvta_generic_to_shared(
                                (const char*)st->Bhi + boff));
                ldsm_x4(bl, (unsigned)__cvta_generic_to_shared(
                                (const char*)st->Blo + boff));
#pragma unroll
                for (int e = 0; e < 2; e++)
#pragma unroll
                    for (int ms = 0; ms < 2; ms++) {
                        mma_f16(acc[ms][p * 2 + e], ah[ms], bh[e], bh[e + 2]);
                        mma_f16(acc[ms][p * 2 + e], ah[ms], bl[e], bl[e + 2]);
                    }
            }
        }
    }

    // ---------------- fused gate epilogue ----------------
    __syncthreads();
    float* zsm = reinterpret_cast<float*>(smem_raw);  // [128][LDZ]

#pragma unroll
    for (int ms = 0; ms < 2; ms++)
#pragma unroll
        for (int ns = 0; ns < 8; ns++) {
            int row = mw + ms * 16 + r;
            int col = nw + ns * 8 + 2 * q;
            *(float2*)&zsm[row * LDZ + col] = make_float2(acc[ms][ns][0], acc[ms][ns][1]);
            *(float2*)&zsm[(row + 8) * LDZ + col] = make_float2(acc[ms][ns][2], acc[ms][ns][3]);
        }
    __syncthreads();

    {
        const int ul = tid & 63;             // local unit 0..63
        const int u = blockIdx.x * 64 + ul;  // global unit
        const float bi = bias[u];
        const float bf = bias[512 + u];
        const float bg = bias[1024 + u];
        const float bo = bias[1536 + u];
        const float pwi = pw[u * 3 + 0];
        const float pwf = pw[u * 3 + 1];
        const float pwo = pw[u * 3 + 2];
#pragma unroll
        for (int it = 0; it < 16; it++) {
            int row = (tid >> 6) * 16 + it;
            int m = m0 + row;
            float4 zz = *reinterpret_cast<const float4*>(&zsm[row * LDZ + ul * 4]);
            float cprev = c_tm1[(size_t)m * UU + u];
            float iv = sigf(zz.x + bi + cprev * pwi);
            float fv = sigf(zz.y + bf + cprev * pwf);
            float gv = tanhf(zz.z + bg);
            float cc = fv * cprev + iv * gv;
            float ov = sigf(zz.w + bo + cc * pwo);
            out[(size_t)m * UU + u] = ov * tanhf(cc);
            out[(size_t)MM * UU + (size_t)m * UU + u] = cc;
        }
    }
}

// ---------------- launch ----------------
extern "C" void kernel_launch(void* const* d_in, const int* in_sizes, int n_in,
                              void* d_out, int out_size) {
    const float* x    = (const float*)d_in[0];
    const float* h    = (const float*)d_in[1];
    const float* c    = (const float*)d_in[2];
    const float* Wk   = (const float*)d_in[3];
    const float* Wr   = (const float*)d_in[4];
    const float* pw   = (const float*)d_in[5];
    const float* bias = (const float*)d_in[6];
    float* out = (float*)d_out;

    cudaFuncSetAttribute(lstm_gemm_kernel, cudaFuncAttributeMaxDynamicSharedMemorySize,
                         (int)(NSTAGES * sizeof(Stage)));

    prep_A_kernel<<<(MM * KK / 8) / 256, 256>>>(x, h);
    prep_B_kernel<<<dim3(NN / 32, KK / 32), dim3(32, 8)>>>(Wk, Wr);
    lstm_gemm_kernel<<<dim3(NN / BN, MM / BM), 512, NSTAGES * sizeof(Stage)>>>(c, pw, bias, out);
}